// round 5
// baseline (speedup 1.0000x reference)
#include <cuda_runtime.h>
#include <cuda_fp16.h>

// Problem constants (fixed by the dataset)
#define BT_  1024   // B*T = 4*256
#define IN_  512
#define OUT_ 512

// Scratch: decoded fp32 operands (no device allocation allowed)
__device__ float g_x[BT_ * IN_];    // 2 MB
__device__ float g_w[OUT_ * IN_];   // 1 MB

// ---------------------------------------------------------------------------
// Packed f32x2 helpers (Blackwell): two independent fp32 FMAs, each rounded
// exactly like scalar FFMA -> preserves bit-exact sequential accumulation.
// ---------------------------------------------------------------------------
__device__ __forceinline__ unsigned long long fma2(unsigned long long a,
                                                   unsigned long long b,
                                                   unsigned long long c) {
    unsigned long long d;
    asm("fma.rn.f32x2 %0, %1, %2, %3;" : "=l"(d) : "l"(a), "l"(b), "l"(c));
    return d;
}
// swap the two f32 halves of a packed pair (2 MOVs, alu pipe)
__device__ __forceinline__ unsigned long long swp2(unsigned long long v) {
    float lo, hi;
    asm("mov.b64 {%0, %1}, %2;" : "=f"(lo), "=f"(hi) : "l"(v));
    unsigned long long r;
    asm("mov.b64 %0, {%1, %2};" : "=l"(r) : "f"(hi), "f"(lo));
    return r;
}

// ---------------------------------------------------------------------------
// Kernel 1: decode pulse bits -> exact fp16 value in fp32.
// 4 elements per thread: 16x LDG.128 in flight, float4 store. HBM-bound.
// Pulse floats are exactly 0.0f or 1.0f, so bit 23 of the raw word is the bit.
// ---------------------------------------------------------------------------
__global__ void decode_kernel(const uint4* __restrict__ xp,
                              const uint4* __restrict__ wp) {
    int t = blockIdx.x * blockDim.x + threadIdx.x;
    const int NX = BT_ * IN_;
    const int NTOT = NX + OUT_ * IN_;
    int e0 = t * 4;
    if (e0 >= NTOT) return;

    const uint4* src;
    float* dst;
    int e;
    if (e0 < NX) { src = xp; dst = g_x; e = e0; }
    else         { src = wp; dst = g_w; e = e0 - NX; }

    uint4 v[16];
#pragma unroll
    for (int q = 0; q < 16; ++q) v[q] = src[(size_t)e * 4 + q];

    float4 r;
    float* rp = &r.x;
#pragma unroll
    for (int h = 0; h < 4; ++h) {
        unsigned u = 0u;
#pragma unroll
        for (int q = 0; q < 4; ++q) {
            uint4 w4 = v[h * 4 + q];
            u |= ((w4.x >> 23) & 1u) << (4 * q + 0);
            u |= ((w4.y >> 23) & 1u) << (4 * q + 1);
            u |= ((w4.z >> 23) & 1u) << (4 * q + 2);
            u |= ((w4.w >> 23) & 1u) << (4 * q + 3);
        }
        rp[h] = __half2float(__ushort_as_half((unsigned short)u));
    }
    *reinterpret_cast<float4*>(dst + e) = r;
}

// ---------------------------------------------------------------------------
// Kernel 2 (fused): bit-exact sequential-k GEMM + RNE fp16 + pulse encode.
//
// Tile 64x64, 256 threads (8 warps -> 2/SMSP), 4x4 micro-tile per thread.
// Diagonal f32x2 pairing: natural x-pairs and w-pairs from two LDS.128 feed
// 8 fma2 per k (4 diagonal + 4 anti-diagonal via one swapped x-pair).
// Inner loop: 2 LDS.128 + 4 MOV + 8 fma2 = 14 instr/k/thread -> per-SMSP
// issue (28 cyc/k) sits under the fma2-pipe floor (32 cyc/k). Double-buffered
// BK=16 with register prefetch.
// ---------------------------------------------------------------------------
#define BM  64
#define BN  64
#define BK  16
#define NT  (IN_ / BK)   // 32 tiles
#define PIT 68           // smem pitch: 64 + 4 floats (rows 16B-aligned)

__device__ __forceinline__ float4 bits4(unsigned u, int s) {
    float4 f;
    f.x = __uint_as_float(((u >> (s + 0)) & 1u) * 0x3F800000u);
    f.y = __uint_as_float(((u >> (s + 1)) & 1u) * 0x3F800000u);
    f.z = __uint_as_float(((u >> (s + 2)) & 1u) * 0x3F800000u);
    f.w = __uint_as_float(((u >> (s + 3)) & 1u) * 0x3F800000u);
    return f;
}

__global__ __launch_bounds__(256) void gemm_enc_kernel(float* __restrict__ out) {
    __shared__ __align__(16) float Xs[2][BK][PIT];   // transposed: [k][m]
    __shared__ __align__(16) float Ws[2][BK][PIT];   // transposed: [k][n]

    const int tid  = threadIdx.x;
    const int row0 = blockIdx.y * BM;
    const int col0 = blockIdx.x * BN;

    const int rg = tid >> 4;    // 0..15 -> rows 4*rg .. 4*rg+3
    const int cg = tid & 15;    // 0..15 -> cols 4*cg .. 4*cg+3

    // accA[p][q] = (C[4rg+2p][4cg+2q],   C[4rg+2p+1][4cg+2q+1])
    // accB[p][q] = (C[4rg+2p+1][4cg+2q], C[4rg+2p][4cg+2q+1])
    unsigned long long accA[2][2] = {}, accB[2][2] = {};

    const float* Xg = g_x + (size_t)row0 * IN_;
    const float* Wg = g_w + (size_t)col0 * IN_;

    // fill mapping: 1 float4 of X + 1 float4 of W per thread per tile
    const int fm  = tid >> 2;   // 0..63 row of the tile
    const int fkq = tid & 3;    // 0..3  k-quad
    const float* srcX = Xg + (size_t)fm * IN_ + fkq * 4;
    const float* srcW = Wg + (size_t)fm * IN_ + fkq * 4;

    float4 px = *reinterpret_cast<const float4*>(srcX);
    float4 pw = *reinterpret_cast<const float4*>(srcW);
    {
        float xv[4] = {px.x, px.y, px.z, px.w};
        float wv[4] = {pw.x, pw.y, pw.z, pw.w};
#pragma unroll
        for (int c = 0; c < 4; ++c) {
            Xs[0][fkq * 4 + c][fm] = xv[c];
            Ws[0][fkq * 4 + c][fm] = wv[c];
        }
    }
    __syncthreads();

    int buf = 0;
    for (int t = 0; t < NT; ++t) {
        // prefetch next tile into registers (latency hidden under compute)
        if (t + 1 < NT) {
            px = *reinterpret_cast<const float4*>(srcX + (t + 1) * BK);
            pw = *reinterpret_cast<const float4*>(srcW + (t + 1) * BK);
        }

        // compute: strictly ascending k for every output element
#pragma unroll
        for (int k = 0; k < BK; ++k) {
            ulonglong2 xv = *reinterpret_cast<const ulonglong2*>(&Xs[buf][k][4 * rg]);
            ulonglong2 wv = *reinterpret_cast<const ulonglong2*>(&Ws[buf][k][4 * cg]);
            unsigned long long s0 = swp2(xv.x);
            unsigned long long s1 = swp2(xv.y);
            accA[0][0] = fma2(xv.x, wv.x, accA[0][0]);
            accA[0][1] = fma2(xv.x, wv.y, accA[0][1]);
            accA[1][0] = fma2(xv.y, wv.x, accA[1][0]);
            accA[1][1] = fma2(xv.y, wv.y, accA[1][1]);
            accB[0][0] = fma2(s0, wv.x, accB[0][0]);
            accB[0][1] = fma2(s0, wv.y, accB[0][1]);
            accB[1][0] = fma2(s1, wv.x, accB[1][0]);
            accB[1][1] = fma2(s1, wv.y, accB[1][1]);
        }

        // stage prefetched registers into the other buffer
        if (t + 1 < NT) {
            float xv[4] = {px.x, px.y, px.z, px.w};
            float wv[4] = {pw.x, pw.y, pw.z, pw.w};
#pragma unroll
            for (int c = 0; c < 4; ++c) {
                Xs[buf ^ 1][fkq * 4 + c][fm] = xv[c];
                Ws[buf ^ 1][fkq * 4 + c][fm] = wv[c];
            }
        }
        __syncthreads();
        buf ^= 1;
    }

    // --- unscramble diagonals into a 4x4 value block ---
    float v[4][4];
#pragma unroll
    for (int p = 0; p < 2; ++p)
#pragma unroll
        for (int q = 0; q < 2; ++q) {
            float aLo, aHi, bLo, bHi;
            asm("mov.b64 {%0, %1}, %2;" : "=f"(aLo), "=f"(aHi) : "l"(accA[p][q]));
            asm("mov.b64 {%0, %1}, %2;" : "=f"(bLo), "=f"(bHi) : "l"(accB[p][q]));
            v[2 * p + 0][2 * q + 0] = aLo;
            v[2 * p + 1][2 * q + 1] = aHi;
            v[2 * p + 1][2 * q + 0] = bLo;
            v[2 * p + 0][2 * q + 1] = bHi;
        }

    // --- fused epilogue: fp32 -> fp16 (RNE) -> 16 pulse bits per output ---
    // Each thread writes 4 rows x 4 consecutive cols = 256B contiguous runs.
    const int cb = col0 + cg * 4;
#pragma unroll
    for (int i = 0; i < 4; ++i) {
        int r = row0 + rg * 4 + i;
        float4* dst = reinterpret_cast<float4*>(out + ((size_t)r * OUT_ + cb) * 16);
#pragma unroll
        for (int c = 0; c < 4; ++c) {
            unsigned u = __half_as_ushort(__float2half_rn(v[i][c]));
#pragma unroll
            for (int q4 = 0; q4 < 4; ++q4)
                dst[c * 4 + q4] = bits4(u, 4 * q4);
        }
    }
}

// ---------------------------------------------------------------------------
extern "C" void kernel_launch(void* const* d_in, const int* in_sizes, int n_in,
                              void* d_out, int out_size) {
    const uint4* xp = (const uint4*)d_in[0];   // x_pulse [4,256,512,16]
    const uint4* wp = (const uint4*)d_in[1];   // w_pulse [512,512,16]
    float* out = (float*)d_out;                // [4,256,512,16]
    (void)in_sizes; (void)n_in; (void)out_size;

    // 1) decode both operand pulse arrays (4 elements / thread)
    const int n_thr = (BT_ * IN_ + OUT_ * IN_) / 4;   // 196608
    decode_kernel<<<(n_thr + 255) / 256, 256>>>(xp, wp);

    // 2) fused bit-exact GEMM + RNE fp16 + pulse-bit encode
    dim3 grid(OUT_ / BN, BT_ / BM);                   // (8, 16) = 128 CTAs
    gemm_enc_kernel<<<grid, 256>>>(out);
}